// round 13
// baseline (speedup 1.0000x reference)
#include <cuda_runtime.h>
#include <cuda_bf16.h>
#include <cstdint>
#include <math.h>

// Normalized embeddings scratch (bf16): 8192 * 256 * 2B = 4 MB, L2-resident.
__device__ __nv_bfloat16 g_en[8192 * 256];

// ---------------------------------------------------------------------------
// Kernel 1: row-normalize embeddings (fp32 -> bf16). One warp per row, D=256.
// Also zeroes the (poisoned) output scalar from block 0.
// ---------------------------------------------------------------------------
__global__ void normalize_kernel(const float* __restrict__ emb, int B,
                                 float* __restrict__ out) {
    if (blockIdx.x == 0 && threadIdx.x == 0) out[0] = 0.0f;

    const int warpId = threadIdx.x >> 5;
    const int lane   = threadIdx.x & 31;
    const int row    = blockIdx.x * 8 + warpId;
    if (row >= B) return;

    const float4* p = reinterpret_cast<const float4*>(emb + (size_t)row * 256);
    float4 v0 = p[lane];
    float4 v1 = p[lane + 32];

    float ss = v0.x * v0.x + v0.y * v0.y + v0.z * v0.z + v0.w * v0.w
             + v1.x * v1.x + v1.y * v1.y + v1.z * v1.z + v1.w * v1.w;
    #pragma unroll
    for (int o = 16; o > 0; o >>= 1) ss += __shfl_xor_sync(0xffffffffu, ss, o);

    const float scale = 1.0f / fmaxf(sqrtf(ss), 1e-8f);

    __nv_bfloat162 a0 = __floats2bfloat162_rn(v0.x * scale, v0.y * scale);
    __nv_bfloat162 a1 = __floats2bfloat162_rn(v0.z * scale, v0.w * scale);
    __nv_bfloat162 b0 = __floats2bfloat162_rn(v1.x * scale, v1.y * scale);
    __nv_bfloat162 b1 = __floats2bfloat162_rn(v1.z * scale, v1.w * scale);

    uint2 ua, ub;
    ua.x = *reinterpret_cast<unsigned*>(&a0);
    ua.y = *reinterpret_cast<unsigned*>(&a1);
    ub.x = *reinterpret_cast<unsigned*>(&b0);
    ub.y = *reinterpret_cast<unsigned*>(&b1);

    uint2* orow = reinterpret_cast<uint2*>(g_en + (size_t)row * 256);
    orow[lane]      = ua;
    orow[lane + 32] = ub;
}

// ---------------------------------------------------------------------------
// Kernel 2: fused cos-GEMM tile + |text - cos| masked reduction.
// BARRIER-FREE compute path:
//   - entire tile staged upfront (4 operand chunks + full text = 215 KB smem,
//     1 CTA/SM) -> no smem reuse -> no __syncthreads needed for WAR safety
//   - per-chunk mbarriers completed via cp.async.mbarrier.arrive.NOINC (the
//     async completion IS the counted arrive; non-noinc increments the pending
//     count at issue and deadlocks -> R12 timeout). Warps try_wait
//     individually and free-run through all 4 chunks + epilogue, skewing so
//     LDSM bursts of one warp overlap MMA blocks of another on the same SMSP.
// Only block syncs: one after mbarrier.init, one in the final reduction.
// ---------------------------------------------------------------------------
#define LDM_OP     72                      // bf16 elems per padded chunk row
#define ROW_BYTES  144
#define STRIP_B    (128 * ROW_BYTES)       // 18432
#define BUF_B      (2 * STRIP_B)           // 36864 (A strip + B strip)
#define LDM_T      132                     // fp32 elems per padded text row
#define TROW_B     528
#define TEXT_OFF   (4 * BUF_B)             // 147456
#define SMEM_TOTAL (TEXT_OFF + 128 * TROW_B)   // 215040

#define LDSM4(R0, R1, R2, R3, ADDR)                                          \
    asm volatile("ldmatrix.sync.aligned.m8n8.x4.shared.b16 {%0,%1,%2,%3}, [%4];" \
                 : "=r"(R0), "=r"(R1), "=r"(R2), "=r"(R3) : "r"(ADDR))

#define MMA16816(C, A, B0, B1)                                               \
    asm volatile("mma.sync.aligned.m16n8k16.row.col.f32.bf16.bf16.f32 "      \
                 "{%0,%1,%2,%3}, {%4,%5,%6,%7}, {%8,%9}, {%0,%1,%2,%3};"     \
                 : "+f"((C)[0]), "+f"((C)[1]), "+f"((C)[2]), "+f"((C)[3])    \
                 : "r"((A)[0]), "r"((A)[1]), "r"((A)[2]), "r"((A)[3]),       \
                   "r"(B0), "r"(B1))

#define CP16(S, G)                                                           \
    asm volatile("cp.async.cg.shared.global [%0], [%1], 16;"                 \
                 :: "r"(S), "l"(G) : "memory")

// Per-thread arrive: triggers on the mbarrier once all of THIS thread's prior
// cp.asyncs have completed. .noinc: counts against the init count (256).
#define CPASYNC_ARRIVE(MBAR)                                                 \
    asm volatile("cp.async.mbarrier.arrive.noinc.shared::cta.b64 [%0];"      \
                 :: "r"(MBAR) : "memory")

#define MBAR_WAIT_P0(MBAR) do {                                              \
    uint32_t _done;                                                          \
    asm volatile("{\n\t.reg .pred p;\n\t"                                    \
                 "mbarrier.try_wait.parity.acquire.cta.shared::cta.b64 p, [%1], 0;\n\t" \
                 "selp.b32 %0, 1, 0, p;\n\t}"                                \
                 : "=r"(_done) : "r"(MBAR) : "memory");                      \
    if (!_done) {                                                            \
        asm volatile("{\n\t.reg .pred P1;\n\t"                               \
                     "W%=:\n\t"                                              \
                     "mbarrier.try_wait.parity.acquire.cta.shared::cta.b64 P1, [%0], 0, 0x989680;\n\t" \
                     "@P1 bra.uni D%=;\n\t"                                  \
                     "bra.uni W%=;\n\t"                                      \
                     "D%=:\n\t}" :: "r"(MBAR) : "memory");                   \
    }                                                                        \
} while (0)

__global__ __launch_bounds__(256, 1)
void loss_kernel(const float* __restrict__ text, float* __restrict__ out,
                 int B, float scale) {
    extern __shared__ char smem[];
    uint32_t sbase;
    asm("{ .reg .u64 t; cvta.to.shared.u64 t, %1; cvt.u32.u64 %0, t; }"
        : "=r"(sbase) : "l"((const void*)smem));

    __shared__ __align__(8) uint64_t mbars[5];   // 4 chunks + text
    __shared__ float red[8];
    uint32_t mb0;
    asm("{ .reg .u64 t; cvta.to.shared.u64 t, %1; cvt.u32.u64 %0, t; }"
        : "=r"(mb0) : "l"((const void*)mbars));

    const int tid = threadIdx.x;

    // ---- linear block id -> upper-triangular (by, bx), by <= bx ----
    const int NT = B >> 7;
    int t = blockIdx.x;
    int by = 0;
    while (t >= NT - by) { t -= NT - by; ++by; }
    const int bx = by + t;

    const char* __restrict__ Ag =
        reinterpret_cast<const char*>(g_en + (size_t)by * 32768);
    const char* __restrict__ Bg =
        reinterpret_cast<const char*>(g_en + (size_t)bx * 32768);
    const char* __restrict__ tg = reinterpret_cast<const char*>(
        text + (size_t)(by * 128) * B + (size_t)bx * 128);

    // ---- init mbarriers (expect 256 noinc-arrivals each) ----
    if (tid == 0) {
        #pragma unroll
        for (int m = 0; m < 5; m++)
            asm volatile("mbarrier.init.shared.b64 [%0], %1;"
                         :: "r"(mb0 + m * 8), "r"(256u) : "memory");
    }
    __syncthreads();   // init visible before any arrive

    // ---- stage ALL 4 operand chunks + full text; arrive per group ----
    #pragma unroll
    for (int ch = 0; ch < 4; ch++) {
        const uint32_t dst = sbase + (uint32_t)ch * BUF_B;
        const size_t gchunk = (size_t)ch * 128;
        #pragma unroll
        for (int i = tid; i < 1024; i += 256) {       // 128 rows x 8 x 16B
            const int r = i >> 3;
            const int c = i & 7;
            const uint32_t soff = (uint32_t)r * ROW_BYTES + (uint32_t)c * 16;
            const size_t   goff = (size_t)r * 512 + gchunk + (size_t)c * 16;
            CP16(dst + soff, Ag + goff);
            CP16(dst + STRIP_B + soff, Bg + goff);
        }
        CPASYNC_ARRIVE(mb0 + ch * 8);
    }
    {
        const uint32_t dst = sbase + (uint32_t)TEXT_OFF;
        #pragma unroll
        for (int i = tid; i < 4096; i += 256) {       // 128 rows x 32 x 16B
            const int r = i >> 5;
            const int c = i & 31;
            CP16(dst + (uint32_t)r * TROW_B + (uint32_t)c * 16,
                 tg + (size_t)r * B * 4 + (size_t)c * 16);
        }
        CPASYNC_ARRIVE(mb0 + 4 * 8);
    }

    // ---- warp / fragment geometry ----
    const int warpId = tid >> 5;
    const int lane   = tid & 31;
    const int wr = warpId & 3;    // 32-row strip
    const int wc = warpId >> 2;   // 64-col strip
    const int grp = lane >> 3;

    const uint32_t aOff =
        (uint32_t)(((wr * 32 + (lane & 15)) * LDM_OP + (lane >> 4) * 8) * 2);
    const uint32_t bOff = (uint32_t)STRIP_B +
        (uint32_t)(((wc * 64 + (grp >> 1) * 8 + (lane & 7)) * LDM_OP + (grp & 1) * 8) * 2);

    float c[2][8][4];
    #pragma unroll
    for (int mt = 0; mt < 2; mt++)
        #pragma unroll
        for (int nt = 0; nt < 8; nt++)
            #pragma unroll
            for (int e = 0; e < 4; e++) c[mt][nt][e] = 0.0f;

    // ---- mainloop: free-running, no block barriers ----
    #pragma unroll
    for (int ch = 0; ch < 4; ch++) {
        MBAR_WAIT_P0(mb0 + ch * 8);
        const uint32_t bufBase = sbase + (uint32_t)ch * BUF_B;
        #pragma unroll
        for (int kc = 0; kc < 4; kc++) {
            const uint32_t koff = (uint32_t)(kc * 32);   // 16 bf16 = 32 B
            uint32_t a[2][4];
            #pragma unroll
            for (int mt = 0; mt < 2; mt++)
                LDSM4(a[mt][0], a[mt][1], a[mt][2], a[mt][3],
                      bufBase + aOff + (uint32_t)(mt * 16 * ROW_BYTES) + koff);
            uint32_t b[4][4];
            #pragma unroll
            for (int p = 0; p < 4; p++)
                LDSM4(b[p][0], b[p][1], b[p][2], b[p][3],
                      bufBase + bOff + (uint32_t)(p * 16 * ROW_BYTES) + koff);
            #pragma unroll
            for (int mt = 0; mt < 2; mt++)
                #pragma unroll
                for (int nt = 0; nt < 8; nt++)
                    MMA16816(c[mt][nt], a[mt],
                             b[nt >> 1][(nt & 1) * 2], b[nt >> 1][(nt & 1) * 2 + 1]);
        }
    }

    // ---- epilogue: |text - cos| with i<j mask (text from smem) ----
    MBAR_WAIT_P0(mb0 + 4 * 8);

    const int qrow = lane >> 2;          // 0..7
    const int qcol = (lane & 3) * 2;     // 0,2,4,6
    const bool diag = (bx == by);
    const float* __restrict__ Ts =
        reinterpret_cast<const float*>(smem + TEXT_OFF);

    float acc = 0.0f;
    #pragma unroll
    for (int mt = 0; mt < 2; mt++) {
        const int r0 = wr * 32 + mt * 16 + qrow;        // tile rows r0, r0+8
        #pragma unroll
        for (int nt = 0; nt < 8; nt++) {
            const int cc = wc * 64 + nt * 8 + qcol;
            const float2 t0 = *reinterpret_cast<const float2*>(Ts + r0 * LDM_T + cc);
            const float2 t1 = *reinterpret_cast<const float2*>(Ts + (r0 + 8) * LDM_T + cc);
            const float* cf = c[mt][nt];
            if (!diag) {
                acc += fabsf(t0.x - cf[0]) + fabsf(t0.y - cf[1])
                     + fabsf(t1.x - cf[2]) + fabsf(t1.y - cf[3]);
            } else {
                if (cc     > r0)     acc += fabsf(t0.x - cf[0]);
                if (cc + 1 > r0)     acc += fabsf(t0.y - cf[1]);
                if (cc     > r0 + 8) acc += fabsf(t1.x - cf[2]);
                if (cc + 1 > r0 + 8) acc += fabsf(t1.y - cf[3]);
            }
        }
    }

    // ---- reduction: warp shuffle -> smem -> one atomicAdd ----
    #pragma unroll
    for (int o = 16; o > 0; o >>= 1) acc += __shfl_xor_sync(0xffffffffu, acc, o);
    if (lane == 0) red[warpId] = acc;
    __syncthreads();
    if (tid == 0) {
        float s = 0.0f;
        #pragma unroll
        for (int w = 0; w < 8; w++) s += red[w];
        atomicAdd(out, s * scale);
    }
}

// ---------------------------------------------------------------------------
// Launch
// ---------------------------------------------------------------------------
extern "C" void kernel_launch(void* const* d_in, const int* in_sizes, int n_in,
                              void* d_out, int out_size) {
    const float* emb  = (const float*)d_in[0];   // [B, D] fp32
    const float* text = (const float*)d_in[1];   // [B, B] fp32
    float* out = (float*)d_out;

    const int B = (int)(sqrt((double)in_sizes[1]) + 0.5);   // 8192
    const double count = (double)B * (double)(B - 1) / 2.0;
    const float scale = (float)(0.1 / count);

    cudaFuncSetAttribute(loss_kernel,
                         cudaFuncAttributeMaxDynamicSharedMemorySize, SMEM_TOTAL);

    normalize_kernel<<<B / 8, 256>>>(emb, B, out);

    const int NT = B / 128;
    const int nblocks = NT * (NT + 1) / 2;   // 2080 upper-tri tiles
    loss_kernel<<<nblocks, 256, SMEM_TOTAL>>>(text, out, B, scale);
}

// round 14
// speedup vs baseline: 1.2625x; 1.2625x over previous
#include <cuda_runtime.h>
#include <cuda_bf16.h>
#include <cstdint>
#include <math.h>

// Normalized embeddings scratch (bf16): 8192 * 256 * 2B = 4 MB, L2-resident.
__device__ __nv_bfloat16 g_en[8192 * 256];

// ---------------------------------------------------------------------------
// Kernel 1: row-normalize embeddings (fp32 -> bf16). One warp per row, D=256.
// Also zeroes the (poisoned) output scalar from block 0.
// ---------------------------------------------------------------------------
__global__ void normalize_kernel(const float* __restrict__ emb, int B,
                                 float* __restrict__ out) {
    if (blockIdx.x == 0 && threadIdx.x == 0) out[0] = 0.0f;

    const int warpId = threadIdx.x >> 5;
    const int lane   = threadIdx.x & 31;
    const int row    = blockIdx.x * 8 + warpId;
    if (row >= B) return;

    const float4* p = reinterpret_cast<const float4*>(emb + (size_t)row * 256);
    float4 v0 = p[lane];
    float4 v1 = p[lane + 32];

    float ss = v0.x * v0.x + v0.y * v0.y + v0.z * v0.z + v0.w * v0.w
             + v1.x * v1.x + v1.y * v1.y + v1.z * v1.z + v1.w * v1.w;
    #pragma unroll
    for (int o = 16; o > 0; o >>= 1) ss += __shfl_xor_sync(0xffffffffu, ss, o);

    const float scale = 1.0f / fmaxf(sqrtf(ss), 1e-8f);

    __nv_bfloat162 a0 = __floats2bfloat162_rn(v0.x * scale, v0.y * scale);
    __nv_bfloat162 a1 = __floats2bfloat162_rn(v0.z * scale, v0.w * scale);
    __nv_bfloat162 b0 = __floats2bfloat162_rn(v1.x * scale, v1.y * scale);
    __nv_bfloat162 b1 = __floats2bfloat162_rn(v1.z * scale, v1.w * scale);

    uint2 ua, ub;
    ua.x = *reinterpret_cast<unsigned*>(&a0);
    ua.y = *reinterpret_cast<unsigned*>(&a1);
    ub.x = *reinterpret_cast<unsigned*>(&b0);
    ub.y = *reinterpret_cast<unsigned*>(&b1);

    uint2* orow = reinterpret_cast<uint2*>(g_en + (size_t)row * 256);
    orow[lane]      = ua;
    orow[lane + 32] = ub;
}

// ---------------------------------------------------------------------------
// Kernel 2: fused cos-GEMM tile + |text - cos| masked reduction.
// BARRIER-FREE pipeline at 2 CTAs/SM:
//   - 3 slots x 32 KB ring (XOR swizzle, no padding): ch0->s0, ch1->s1,
//     ch2->s2, ch3->s0, text[0:64)->s1, text[64:128)->s2 (halves = 32 KB).
//   - full[] barriers: cp.async.mbarrier.arrive.noinc (256 per-thread async
//     completions). empty[] barriers: plain arrives after each thread's last
//     read of a slot. All waits are per-thread try_wait -> warps free-run;
//     NO __syncthreads between first MMA and the final reduction.
//   - swizzle keys are per-lane constants (rows are multiples of 8).
// smem = 3 x 32768 = 98304 -> 2 CTAs/SM (16 warps).
// ---------------------------------------------------------------------------
#define SLOT_B   32768
#define STRIP    16384                     // A strip size within a slot
#define SMEM_TOTAL (3 * SLOT_B)            // 98304

#define LDSM4(R0, R1, R2, R3, ADDR)                                          \
    asm volatile("ldmatrix.sync.aligned.m8n8.x4.shared.b16 {%0,%1,%2,%3}, [%4];" \
                 : "=r"(R0), "=r"(R1), "=r"(R2), "=r"(R3) : "r"(ADDR))

#define MMA16816(C, A, B0, B1)                                               \
    asm volatile("mma.sync.aligned.m16n8k16.row.col.f32.bf16.bf16.f32 "      \
                 "{%0,%1,%2,%3}, {%4,%5,%6,%7}, {%8,%9}, {%0,%1,%2,%3};"     \
                 : "+f"((C)[0]), "+f"((C)[1]), "+f"((C)[2]), "+f"((C)[3])    \
                 : "r"((A)[0]), "r"((A)[1]), "r"((A)[2]), "r"((A)[3]),       \
                   "r"(B0), "r"(B1))

#define CP16(S, G)                                                           \
    asm volatile("cp.async.cg.shared.global [%0], [%1], 16;"                 \
                 :: "r"(S), "l"(G) : "memory")

#define ARRIVE_NOINC(MBAR)                                                   \
    asm volatile("cp.async.mbarrier.arrive.noinc.shared::cta.b64 [%0];"      \
                 :: "r"(MBAR) : "memory")

#define ARRIVE(MBAR)                                                         \
    asm volatile("mbarrier.arrive.shared::cta.b64 _, [%0];"                  \
                 :: "r"(MBAR) : "memory")

#define MBAR_WAIT_P0(MBAR) do {                                              \
    uint32_t _done;                                                          \
    asm volatile("{\n\t.reg .pred p;\n\t"                                    \
                 "mbarrier.try_wait.parity.acquire.cta.shared::cta.b64 p, [%1], 0;\n\t" \
                 "selp.b32 %0, 1, 0, p;\n\t}"                                \
                 : "=r"(_done) : "r"(MBAR) : "memory");                      \
    if (!_done) {                                                            \
        asm volatile("{\n\t.reg .pred P1;\n\t"                               \
                     "W%=:\n\t"                                              \
                     "mbarrier.try_wait.parity.acquire.cta.shared::cta.b64 P1, [%0], 0, 0x989680;\n\t" \
                     "@P1 bra.uni D%=;\n\t"                                  \
                     "bra.uni W%=;\n\t"                                      \
                     "D%=:\n\t}" :: "r"(MBAR) : "memory");                   \
    }                                                                        \
} while (0)

// Stage one K=64 operand chunk (A + B strips, swizzled 128 B rows) into slot.
__device__ __forceinline__ void stage_op(uint32_t slot, int ch,
                                         const char* Ag, const char* Bg,
                                         int tid) {
    #pragma unroll
    for (int i = tid; i < 1024; i += 256) {          // 128 rows x 8 x 16B
        const int r = i >> 3;
        const int c = i & 7;
        const uint32_t soff = (uint32_t)r * 128 + (uint32_t)((c ^ (r & 7)) << 4);
        const size_t   goff = (size_t)r * 512 + (size_t)ch * 128 + (size_t)c * 16;
        CP16(slot + soff, Ag + goff);
        CP16(slot + STRIP + soff, Bg + goff);
    }
}

// Stage 64 text rows (512 B each, swizzled 16B chunks) into a 32 KB slot.
__device__ __forceinline__ void stage_text(uint32_t slot, const char* tg,
                                           int B, int tid) {
    #pragma unroll
    for (int i = tid; i < 2048; i += 256) {          // 64 rows x 32 x 16B
        const int r = i >> 5;
        const int c = i & 31;
        const uint32_t soff = (uint32_t)r * 512 + (uint32_t)((c ^ (r & 7)) << 4);
        CP16(slot + soff, tg + (size_t)r * B * 4 + (size_t)c * 16);
    }
}

// One K=64 chunk of MMAs from the given slot (swizzled addressing).
__device__ __forceinline__ void mma_chunk(uint32_t slot, uint32_t aRow,
                                          uint32_t bRow, uint32_t aHi,
                                          uint32_t bHi, uint32_t s7,
                                          float c[2][8][4]) {
    #pragma unroll
    for (int kc = 0; kc < 4; kc++) {
        uint32_t a[2][4];
        #pragma unroll
        for (int mt = 0; mt < 2; mt++)
            LDSM4(a[mt][0], a[mt][1], a[mt][2], a[mt][3],
                  slot + aRow + (uint32_t)(mt * 2048)
                       + (uint32_t)((((kc * 2) + aHi) ^ s7) << 4));
        uint32_t b[4][4];
        #pragma unroll
        for (int p = 0; p < 4; p++)
            LDSM4(b[p][0], b[p][1], b[p][2], b[p][3],
                  slot + STRIP + bRow + (uint32_t)(p * 2048)
                       + (uint32_t)((((kc * 2) + bHi) ^ s7) << 4));
        #pragma unroll
        for (int mt = 0; mt < 2; mt++)
            #pragma unroll
            for (int nt = 0; nt < 8; nt++)
                MMA16816(c[mt][nt], a[mt],
                         b[nt >> 1][(nt & 1) * 2], b[nt >> 1][(nt & 1) * 2 + 1]);
    }
}

__global__ __launch_bounds__(256, 2)
void loss_kernel(const float* __restrict__ text, float* __restrict__ out,
                 int B, float scale) {
    extern __shared__ char smem[];
    uint32_t sbase;
    asm("{ .reg .u64 t; cvta.to.shared.u64 t, %1; cvt.u32.u64 %0, t; }"
        : "=r"(sbase) : "l"((const void*)smem));

    __shared__ __align__(8) uint64_t mbars[9];   // f0..f5, e0..e2
    __shared__ float red[8];
    uint32_t mb0;
    asm("{ .reg .u64 t; cvta.to.shared.u64 t, %1; cvt.u32.u64 %0, t; }"
        : "=r"(mb0) : "l"((const void*)mbars));
    #define FB(i) (mb0 + (i) * 8)          // full barrier i (stage i)
    #define EB(i) (mb0 + 48 + (i) * 8)     // empty barrier for slot i

    const int tid = threadIdx.x;

    // ---- linear block id -> upper-triangular (by, bx), by <= bx ----
    const int NT = B >> 7;
    int t = blockIdx.x;
    int by = 0;
    while (t >= NT - by) { t -= NT - by; ++by; }
    const int bx = by + t;

    const char* __restrict__ Ag =
        reinterpret_cast<const char*>(g_en + (size_t)by * 32768);
    const char* __restrict__ Bg =
        reinterpret_cast<const char*>(g_en + (size_t)bx * 32768);
    const char* __restrict__ tg = reinterpret_cast<const char*>(
        text + (size_t)(by * 128) * B + (size_t)bx * 128);

    // ---- init barriers (all expect 256 arrivals) ----
    if (tid == 0) {
        #pragma unroll
        for (int m = 0; m < 9; m++)
            asm volatile("mbarrier.init.shared.b64 [%0], %1;"
                         :: "r"(mb0 + m * 8), "r"(256u) : "memory");
    }
    __syncthreads();   // init visible before any arrive

    const uint32_t s0 = sbase, s1 = sbase + SLOT_B, s2 = sbase + 2 * SLOT_B;

    // ---- prologue staging: ch0->s0, ch1->s1, ch2->s2 ----
    stage_op(s0, 0, Ag, Bg, tid);  ARRIVE_NOINC(FB(0));
    stage_op(s1, 1, Ag, Bg, tid);  ARRIVE_NOINC(FB(1));
    stage_op(s2, 2, Ag, Bg, tid);  ARRIVE_NOINC(FB(2));

    // ---- warp / fragment geometry ----
    const int warpId = tid >> 5;
    const int lane   = tid & 31;
    const int wr = warpId & 3;    // 32-row strip
    const int wc = warpId >> 2;   // 64-col strip
    const int grp = lane >> 3;

    const uint32_t aRow = (uint32_t)((wr * 32 + (lane & 15)) * 128);
    const uint32_t bRow = (uint32_t)((wc * 64 + (grp >> 1) * 8 + (lane & 7)) * 128);
    const uint32_t aHi  = (uint32_t)(lane >> 4);
    const uint32_t bHi  = (uint32_t)(grp & 1);
    const uint32_t s7   = (uint32_t)(lane & 7);

    float c[2][8][4];
    #pragma unroll
    for (int mt = 0; mt < 2; mt++)
        #pragma unroll
        for (int nt = 0; nt < 8; nt++)
            #pragma unroll
            for (int e = 0; e < 4; e++) c[mt][nt][e] = 0.0f;

    // ---- free-running pipeline (no __syncthreads until reduction) ----
    MBAR_WAIT_P0(FB(0));  mma_chunk(s0, aRow, bRow, aHi, bHi, s7, c);  ARRIVE(EB(0));
    MBAR_WAIT_P0(FB(1));  mma_chunk(s1, aRow, bRow, aHi, bHi, s7, c);  ARRIVE(EB(1));

    MBAR_WAIT_P0(EB(0));                       // all reads of ch0 done
    stage_op(s0, 3, Ag, Bg, tid);  ARRIVE_NOINC(FB(3));

    MBAR_WAIT_P0(FB(2));  mma_chunk(s2, aRow, bRow, aHi, bHi, s7, c);  ARRIVE(EB(2));

    MBAR_WAIT_P0(EB(1));                       // all reads of ch1 done
    stage_text(s1, tg, B, tid);                ARRIVE_NOINC(FB(4));
    MBAR_WAIT_P0(EB(2));                       // all reads of ch2 done
    stage_text(s2, tg + (size_t)64 * B * 4, B, tid);  ARRIVE_NOINC(FB(5));

    MBAR_WAIT_P0(FB(3));  mma_chunk(s0, aRow, bRow, aHi, bHi, s7, c);

    // ---- epilogue: |text - cos| with i<j mask (swizzled smem text) ----
    MBAR_WAIT_P0(wr < 2 ? FB(4) : FB(5));      // only the half this warp reads

    const int qrow = lane >> 2;          // 0..7
    const int qcol = (lane & 3) * 2;     // 0,2,4,6
    const bool diag = (bx == by);
    const uint32_t tslot_off = (wr < 2) ? (uint32_t)SLOT_B : (uint32_t)(2 * SLOT_B);
    const char* __restrict__ Tb = smem + tslot_off;

    float acc = 0.0f;
    #pragma unroll
    for (int mt = 0; mt < 2; mt++) {
        const int r0 = wr * 32 + mt * 16 + qrow;        // tile rows r0, r0+8
        const int lr = r0 & 63;                          // row within half
        #pragma unroll
        for (int nt = 0; nt < 8; nt++) {
            const int cc = wc * 64 + nt * 8 + qcol;
            const uint32_t chunk = (uint32_t)(cc >> 2);
            const uint32_t off = (uint32_t)lr * 512
                               + ((chunk ^ (uint32_t)qrow) << 4)
                               + (uint32_t)((cc & 3) * 4);
            const float2 t0 = *reinterpret_cast<const float2*>(Tb + off);
            const float2 t1 = *reinterpret_cast<const float2*>(Tb + off + 4096);
            const float* cf = c[mt][nt];
            if (!diag) {
                acc += fabsf(t0.x - cf[0]) + fabsf(t0.y - cf[1])
                     + fabsf(t1.x - cf[2]) + fabsf(t1.y - cf[3]);
            } else {
                if (cc     > r0)     acc += fabsf(t0.x - cf[0]);
                if (cc + 1 > r0)     acc += fabsf(t0.y - cf[1]);
                if (cc     > r0 + 8) acc += fabsf(t1.x - cf[2]);
                if (cc + 1 > r0 + 8) acc += fabsf(t1.y - cf[3]);
            }
        }
    }

    // ---- reduction: warp shuffle -> smem -> one atomicAdd ----
    #pragma unroll
    for (int o = 16; o > 0; o >>= 1) acc += __shfl_xor_sync(0xffffffffu, acc, o);
    if (lane == 0) red[warpId] = acc;
    __syncthreads();
    if (tid == 0) {
        float s = 0.0f;
        #pragma unroll
        for (int w = 0; w < 8; w++) s += red[w];
        atomicAdd(out, s * scale);
    }
}

// ---------------------------------------------------------------------------
// Launch
// ---------------------------------------------------------------------------
extern "C" void kernel_launch(void* const* d_in, const int* in_sizes, int n_in,
                              void* d_out, int out_size) {
    const float* emb  = (const float*)d_in[0];   // [B, D] fp32
    const float* text = (const float*)d_in[1];   // [B, B] fp32
    float* out = (float*)d_out;

    const int B = (int)(sqrt((double)in_sizes[1]) + 0.5);   // 8192
    const double count = (double)B * (double)(B - 1) / 2.0;
    const float scale = (float)(0.1 / count);

    cudaFuncSetAttribute(loss_kernel,
                         cudaFuncAttributeMaxDynamicSharedMemorySize, SMEM_TOTAL);

    normalize_kernel<<<B / 8, 256>>>(emb, B, out);

    const int NT = B / 128;
    const int nblocks = NT * (NT + 1) / 2;   // 2080 upper-tri tiles
    loss_kernel<<<nblocks, 256, SMEM_TOTAL>>>(text, out, B, scale);
}